// round 1
// baseline (speedup 1.0000x reference)
#include <cuda_runtime.h>
#include <cuda_bf16.h>
#include <cstdint>
#include <math.h>

// Problem dims (fixed by the dataset)
constexpr int S  = 8192;   // B*T tokens
constexpr int D  = 2048;   // model dim
constexpr int H  = 2048;   // expert hidden
constexpr int E  = 8;      // experts
constexpr int KK = 2;      // top-k
constexpr int CAP = 2048;  // per-expert capacity
constexpr int B  = 4;
constexpr int T  = 2048;
constexpr int NTILES = H / 128;  // 16 N-tiles per expert row

// ---------------- device scratch (no allocations allowed) ----------------
__device__ int   g_eid[KK * S];
__device__ float g_wgt[KK * S];
__device__ int   g_src[E * CAP];       // slot -> source token (-1 = empty)
__device__ int   g_tokslot[KK * S];    // (k,s) -> slot index or -1
__device__ float g_w2sum[E * H];
__device__ float g_b2sum[E];
__device__ float g_part[(size_t)E * CAP * NTILES];
__device__ float g_logit[S];

// ---------------- K0: row sums of w2 (and b2) --------------------------
__global__ void k_rowsum(const float* __restrict__ src, float* __restrict__ dst,
                         int nrows) {
    int gw   = (blockIdx.x * blockDim.x + threadIdx.x) >> 5;
    int lane = threadIdx.x & 31;
    if (gw >= nrows) return;
    const float* row = src + (size_t)gw * D;
    float s = 0.f;
    #pragma unroll
    for (int d = lane * 4; d < D; d += 32 * 4) {
        float4 v = *(const float4*)(row + d);
        s += v.x + v.y + v.z + v.w;
    }
    #pragma unroll
    for (int o = 16; o; o >>= 1) s += __shfl_xor_sync(0xffffffffu, s, o);
    if (lane == 0) dst[gw] = s;
}

// ---------------- K1: gating (top-2 of softmax(x@wg), normalized) ------
__global__ void k_gate(const float* __restrict__ x, const float* __restrict__ wg) {
    int warp = (blockIdx.x * blockDim.x + threadIdx.x) >> 5;
    int lane = threadIdx.x & 31;
    if (warp >= S) return;
    const float* xr = x + (size_t)warp * D;
    float acc[8] = {0, 0, 0, 0, 0, 0, 0, 0};
    for (int d = lane; d < D; d += 32) {
        float xv = xr[d];
        const float* wr = wg + (size_t)d * 8;
        float4 w0 = *(const float4*)wr;
        float4 w1 = *(const float4*)(wr + 4);
        acc[0] = fmaf(xv, w0.x, acc[0]);
        acc[1] = fmaf(xv, w0.y, acc[1]);
        acc[2] = fmaf(xv, w0.z, acc[2]);
        acc[3] = fmaf(xv, w0.w, acc[3]);
        acc[4] = fmaf(xv, w1.x, acc[4]);
        acc[5] = fmaf(xv, w1.y, acc[5]);
        acc[6] = fmaf(xv, w1.z, acc[6]);
        acc[7] = fmaf(xv, w1.w, acc[7]);
    }
    #pragma unroll
    for (int ee = 0; ee < 8; ee++)
        #pragma unroll
        for (int o = 16; o; o >>= 1)
            acc[ee] += __shfl_xor_sync(0xffffffffu, acc[ee], o);
    if (lane == 0) {
        // top-1 (strict > keeps lowest index on ties, matching lax.top_k)
        int i0 = 0; float v0 = acc[0];
        #pragma unroll
        for (int ee = 1; ee < 8; ee++)
            if (acc[ee] > v0) { v0 = acc[ee]; i0 = ee; }
        int i1 = -1; float v1 = -INFINITY;
        #pragma unroll
        for (int ee = 0; ee < 8; ee++)
            if (ee != i0 && acc[ee] > v1) { v1 = acc[ee]; i1 = ee; }
        // normalized top-2 softmax weights: w0 = e^{v0}/(e^{v0}+e^{v1})
        float w0 = 1.f / (1.f + __expf(0.f) * expf(v1 - v0));
        g_eid[warp]     = i0;
        g_eid[S + warp] = i1;
        g_wgt[warp]     = w0;
        g_wgt[S + warp] = 1.f - w0;
    }
}

// ---------------- K2: capacity-aware slot assignment (one block) -------
// Exact k-major, s-minor rank per expert (matches cumsum semantics).
__global__ void k_assign() {
    __shared__ int hist[256][8];
    const int t = threadIdx.x;
    // init slot map
    for (int i = t; i < E * CAP; i += 256) g_src[i] = -1;
    // local histogram over this thread's 64 consecutive (k-major) entries
    int h[8] = {0, 0, 0, 0, 0, 0, 0, 0};
    const int base = t * 64;
    for (int j = 0; j < 64; j++) h[g_eid[base + j]]++;
    #pragma unroll
    for (int ee = 0; ee < 8; ee++) hist[t][ee] = h[ee];
    __syncthreads();
    // exclusive scan over chunks, per expert (serial, tiny)
    if (t < 8) {
        int run = 0;
        for (int c = 0; c < 256; c++) {
            int v = hist[c][t];
            hist[c][t] = run;
            run += v;
        }
    }
    __syncthreads();
    int cnt[8];
    #pragma unroll
    for (int ee = 0; ee < 8; ee++) cnt[ee] = hist[t][ee];
    for (int j = 0; j < 64; j++) {
        int n = base + j;
        int e = g_eid[n];
        int loc = cnt[e]++;
        if (loc < CAP) {
            g_src[e * CAP + loc] = n & (S - 1);  // token s
            g_tokslot[n] = e * CAP + loc;
        } else {
            g_tokslot[n] = -1;
        }
    }
}

// ---------------- K3: fused expert GEMM + epilogue reduction -----------
// grid = (H/128, CAP/128, E). Block computes 128x128 tile of
// h = relu(gather(x) @ w1[e] + b1[e]) and reduces h . w2sum[e] per row,
// writing one partial per (slot, n-tile) into g_part. No atomics.
__global__ void __launch_bounds__(256, 2)
k_ffn(const float* __restrict__ x, const float* __restrict__ w1,
      const float* __restrict__ b1) {
    const int e  = blockIdx.z;
    const int m0 = blockIdx.y * 128;
    const int n0 = blockIdx.x * 128;
    const int t  = threadIdx.x;

    __shared__ float As[2][8][132];  // padded (+4) to dodge STS conflicts
    __shared__ float Bs[2][8][128];

    // A loader: 128 rows x 8 k per tile; 2 threads per row
    const int arow  = t >> 1;
    const int ahalf = (t & 1) * 4;
    const int stok  = g_src[e * CAP + m0 + arow];
    const float* aptr = (stok >= 0) ? (x + (size_t)stok * D + ahalf) : nullptr;

    // B loader: 8 k x 128 n per tile
    const int bk = t >> 5;
    const int bn = (t & 31) * 4;
    const float* bptr = w1 + ((size_t)e * D + bk) * H + n0 + bn;

    float4 areg = make_float4(0.f, 0.f, 0.f, 0.f);
    if (aptr) areg = *(const float4*)aptr;
    float4 breg = *(const float4*)bptr;

    As[0][ahalf + 0][arow] = areg.x;
    As[0][ahalf + 1][arow] = areg.y;
    As[0][ahalf + 2][arow] = areg.z;
    As[0][ahalf + 3][arow] = areg.w;
    *(float4*)&Bs[0][bk][bn] = breg;
    __syncthreads();

    const int ty = t >> 4, tx = t & 15;
    float acc[8][8];
    #pragma unroll
    for (int i = 0; i < 8; i++)
        #pragma unroll
        for (int j = 0; j < 8; j++) acc[i][j] = 0.f;

    int buf = 0;
    for (int kk = 8; kk <= D; kk += 8) {
        const bool more = (kk < D);
        if (more) {
            areg = make_float4(0.f, 0.f, 0.f, 0.f);
            if (aptr) areg = *(const float4*)(aptr + kk);
            breg = *(const float4*)(bptr + (size_t)kk * H);
        }
        #pragma unroll
        for (int k = 0; k < 8; k++) {
            float a[8], b[8];
            *(float4*)&a[0] = *(const float4*)&As[buf][k][ty * 8];
            *(float4*)&a[4] = *(const float4*)&As[buf][k][ty * 8 + 4];
            *(float4*)&b[0] = *(const float4*)&Bs[buf][k][tx * 8];
            *(float4*)&b[4] = *(const float4*)&Bs[buf][k][tx * 8 + 4];
            #pragma unroll
            for (int i = 0; i < 8; i++)
                #pragma unroll
                for (int j = 0; j < 8; j++)
                    acc[i][j] = fmaf(a[i], b[j], acc[i][j]);
        }
        if (more) {
            const int nb = buf ^ 1;
            As[nb][ahalf + 0][arow] = areg.x;
            As[nb][ahalf + 1][arow] = areg.y;
            As[nb][ahalf + 2][arow] = areg.z;
            As[nb][ahalf + 3][arow] = areg.w;
            *(float4*)&Bs[nb][bk][bn] = breg;
        }
        __syncthreads();
        buf ^= 1;
    }

    // Epilogue: relu(acc + b1) . w2sum, reduced across the 16 tx columns.
    float bv[8], wv[8];
    {
        const float* bp = b1 + (size_t)e * H + n0 + tx * 8;
        const float* wp = g_w2sum + (size_t)e * H + n0 + tx * 8;
        *(float4*)&bv[0] = *(const float4*)bp;
        *(float4*)&bv[4] = *(const float4*)(bp + 4);
        *(float4*)&wv[0] = *(const float4*)wp;
        *(float4*)&wv[4] = *(const float4*)(wp + 4);
    }
    float* red = &As[0][0][0];  // 2112 floats available, need 2048
    #pragma unroll
    for (int i = 0; i < 8; i++) {
        float sr = 0.f;
        #pragma unroll
        for (int j = 0; j < 8; j++)
            sr += fmaxf(acc[i][j] + bv[j], 0.f) * wv[j];
        red[tx * 128 + ty * 8 + i] = sr;
    }
    __syncthreads();
    if (t < 128) {
        float ssum = 0.f;
        #pragma unroll
        for (int q = 0; q < 16; q++) ssum += red[q * 128 + t];
        g_part[(size_t)(e * CAP + m0 + t) * NTILES + blockIdx.x] = ssum;
    }
}

// ---------------- K4a: per-token logit = sum over D of y ----------------
__global__ void k_logit() {
    int s = blockIdx.x * blockDim.x + threadIdx.x;
    if (s >= S) return;
    float l = 0.f;
    #pragma unroll
    for (int k = 0; k < KK; k++) {
        int slot = g_tokslot[k * S + s];
        if (slot >= 0) {
            float c = 0.f;
            const float* p = g_part + (size_t)slot * NTILES;
            #pragma unroll
            for (int j = 0; j < NTILES; j++) c += p[j];
            l += g_wgt[k * S + s] * (c + g_b2sum[g_eid[k * S + s]]);
        }
    }
    g_logit[s] = l;
}

// ---------------- K4b: log_softmax over T per batch row -----------------
__global__ void k_lsm(float* __restrict__ out) {
    const int b = blockIdx.x;
    const int t = threadIdx.x;  // 256 threads
    __shared__ float sh[256];
    const float* lr = g_logit + (size_t)b * T;
    float v[8];
    float mx = -INFINITY;
    #pragma unroll
    for (int i = 0; i < 8; i++) {
        v[i] = lr[t + i * 256];
        mx = fmaxf(mx, v[i]);
    }
    sh[t] = mx;
    __syncthreads();
    for (int o = 128; o; o >>= 1) {
        if (t < o) sh[t] = fmaxf(sh[t], sh[t + o]);
        __syncthreads();
    }
    mx = sh[0];
    __syncthreads();
    float se = 0.f;
    #pragma unroll
    for (int i = 0; i < 8; i++) se += expf(v[i] - mx);
    sh[t] = se;
    __syncthreads();
    for (int o = 128; o; o >>= 1) {
        if (t < o) sh[t] += sh[t + o];
        __syncthreads();
    }
    float lse = logf(sh[0]) + mx;
    #pragma unroll
    for (int i = 0; i < 8; i++)
        out[(size_t)b * T + t + i * 256] = v[i] - lse;
}

// ---------------- launch ------------------------------------------------
extern "C" void kernel_launch(void* const* d_in, const int* in_sizes, int n_in,
                              void* d_out, int out_size) {
    const float* x  = (const float*)d_in[0];   // [B,T,D]
    const float* wg = (const float*)d_in[1];   // [D,E]
    const float* w1 = (const float*)d_in[2];   // [E,D,H]
    const float* b1 = (const float*)d_in[3];   // [E,H]
    const float* w2 = (const float*)d_in[4];   // [E,H,D]
    const float* b2 = (const float*)d_in[5];   // [E,D]
    float* out = (float*)d_out;                // [B,T]
    (void)in_sizes; (void)n_in; (void)out_size;

    float* w2sum_p; cudaGetSymbolAddress((void**)&w2sum_p, g_w2sum);
    float* b2sum_p; cudaGetSymbolAddress((void**)&b2sum_p, g_b2sum);

    // K0: w2 row sums (E*H rows of length D) and b2 sums (E rows)
    k_rowsum<<<(E * H) / 8, 256>>>(w2, w2sum_p, E * H);
    k_rowsum<<<1, 256>>>(b2, b2sum_p, E);

    // K1: gating, one warp per token
    k_gate<<<S / 8, 256>>>(x, wg);

    // K2: deterministic capacity assignment, single block
    k_assign<<<1, 256>>>();

    // K3: grouped expert GEMM + fused reduction
    dim3 g3(H / 128, CAP / 128, E);
    k_ffn<<<g3, 256>>>(x, w1, b1);

    // K4: combine + log_softmax
    k_logit<<<S / 256, 256>>>();
    k_lsm<<<B, 256>>>(out);
}

// round 2
// speedup vs baseline: 1.0554x; 1.0554x over previous
#include <cuda_runtime.h>
#include <cuda_bf16.h>
#include <cstdint>
#include <math.h>

// Problem dims (fixed by the dataset)
constexpr int S  = 8192;   // B*T tokens
constexpr int D  = 2048;   // model dim
constexpr int H  = 2048;   // expert hidden
constexpr int E  = 8;      // experts
constexpr int KK = 2;      // top-k
constexpr int CAP = 2048;  // per-expert capacity
constexpr int B  = 4;
constexpr int T  = 2048;
constexpr int NTILES = H / 128;  // 16 N-tiles per expert row

// ---------------- device scratch (no allocations allowed) ----------------
__device__ int   g_eid[KK * S];
__device__ float g_wgt[KK * S];
__device__ int   g_src[E * CAP];       // slot -> source token (-1 = empty)
__device__ int   g_tokslot[KK * S];    // (k,s) -> slot index or -1
__device__ float g_w2sum[E * H];
__device__ float g_b2sum[E];
__device__ float g_part[(size_t)E * CAP * NTILES];
__device__ float g_logit[S];

// ---------------- K0: row sums of w2 (and b2) --------------------------
__global__ void k_rowsum(const float* __restrict__ src, float* __restrict__ dst,
                         int nrows) {
    int gw   = (blockIdx.x * blockDim.x + threadIdx.x) >> 5;
    int lane = threadIdx.x & 31;
    if (gw >= nrows) return;
    const float* row = src + (size_t)gw * D;
    float s = 0.f;
    #pragma unroll
    for (int d = lane * 4; d < D; d += 32 * 4) {
        float4 v = *(const float4*)(row + d);
        s += v.x + v.y + v.z + v.w;
    }
    #pragma unroll
    for (int o = 16; o; o >>= 1) s += __shfl_xor_sync(0xffffffffu, s, o);
    if (lane == 0) dst[gw] = s;
}

// ---------------- K1: gating (top-2 of softmax(x@wg), normalized) ------
__global__ void k_gate(const float* __restrict__ x, const float* __restrict__ wg) {
    int warp = (blockIdx.x * blockDim.x + threadIdx.x) >> 5;
    int lane = threadIdx.x & 31;
    if (warp >= S) return;
    const float* xr = x + (size_t)warp * D;
    float acc[8] = {0, 0, 0, 0, 0, 0, 0, 0};
    for (int d = lane; d < D; d += 32) {
        float xv = xr[d];
        const float* wr = wg + (size_t)d * 8;
        float4 w0 = *(const float4*)wr;
        float4 w1 = *(const float4*)(wr + 4);
        acc[0] = fmaf(xv, w0.x, acc[0]);
        acc[1] = fmaf(xv, w0.y, acc[1]);
        acc[2] = fmaf(xv, w0.z, acc[2]);
        acc[3] = fmaf(xv, w0.w, acc[3]);
        acc[4] = fmaf(xv, w1.x, acc[4]);
        acc[5] = fmaf(xv, w1.y, acc[5]);
        acc[6] = fmaf(xv, w1.z, acc[6]);
        acc[7] = fmaf(xv, w1.w, acc[7]);
    }
    #pragma unroll
    for (int ee = 0; ee < 8; ee++)
        #pragma unroll
        for (int o = 16; o; o >>= 1)
            acc[ee] += __shfl_xor_sync(0xffffffffu, acc[ee], o);
    if (lane == 0) {
        // top-1 (strict > keeps lowest index on ties, matching lax.top_k)
        int i0 = 0; float v0 = acc[0];
        #pragma unroll
        for (int ee = 1; ee < 8; ee++)
            if (acc[ee] > v0) { v0 = acc[ee]; i0 = ee; }
        int i1 = -1; float v1 = -INFINITY;
        #pragma unroll
        for (int ee = 0; ee < 8; ee++)
            if (ee != i0 && acc[ee] > v1) { v1 = acc[ee]; i1 = ee; }
        // normalized top-2 softmax weights: w0 = e^{v0}/(e^{v0}+e^{v1})
        float w0 = 1.f / (1.f + __expf(0.f) * expf(v1 - v0));
        g_eid[warp]     = i0;
        g_eid[S + warp] = i1;
        g_wgt[warp]     = w0;
        g_wgt[S + warp] = 1.f - w0;
    }
}

// ---------------- K2: capacity-aware slot assignment (one block) -------
// Exact k-major, s-minor rank per expert (matches cumsum semantics).
__global__ void k_assign() {
    __shared__ int hist[256][8];
    const int t = threadIdx.x;
    // init slot map
    for (int i = t; i < E * CAP; i += 256) g_src[i] = -1;
    // local histogram over this thread's 64 consecutive (k-major) entries
    int h[8] = {0, 0, 0, 0, 0, 0, 0, 0};
    const int base = t * 64;
    for (int j = 0; j < 64; j++) h[g_eid[base + j]]++;
    #pragma unroll
    for (int ee = 0; ee < 8; ee++) hist[t][ee] = h[ee];
    __syncthreads();
    // exclusive scan over chunks, per expert (serial, tiny)
    if (t < 8) {
        int run = 0;
        for (int c = 0; c < 256; c++) {
            int v = hist[c][t];
            hist[c][t] = run;
            run += v;
        }
    }
    __syncthreads();
    int cnt[8];
    #pragma unroll
    for (int ee = 0; ee < 8; ee++) cnt[ee] = hist[t][ee];
    for (int j = 0; j < 64; j++) {
        int n = base + j;
        int e = g_eid[n];
        int loc = cnt[e]++;
        if (loc < CAP) {
            g_src[e * CAP + loc] = n & (S - 1);  // token s
            g_tokslot[n] = e * CAP + loc;
        } else {
            g_tokslot[n] = -1;
        }
    }
}

// ---------------- K3: fused expert GEMM + epilogue reduction -----------
// grid = (H/128, CAP/128, E). Block computes 128x128 tile of
// h = relu(gather(x) @ w1[e] + b1[e]) and reduces h . w2sum[e] per row,
// writing one partial per (slot, n-tile) into g_part. No atomics.
__global__ void __launch_bounds__(256, 2)
k_ffn(const float* __restrict__ x, const float* __restrict__ w1,
      const float* __restrict__ b1) {
    const int e  = blockIdx.z;
    const int m0 = blockIdx.y * 128;
    const int n0 = blockIdx.x * 128;
    const int t  = threadIdx.x;

    __shared__ float As[2][8][132];  // padded (+4) to dodge STS conflicts
    __shared__ float Bs[2][8][128];

    // A loader: 128 rows x 8 k per tile; 2 threads per row
    const int arow  = t >> 1;
    const int ahalf = (t & 1) * 4;
    const int stok  = g_src[e * CAP + m0 + arow];
    const float* aptr = (stok >= 0) ? (x + (size_t)stok * D + ahalf) : nullptr;

    // B loader: 8 k x 128 n per tile
    const int bk = t >> 5;
    const int bn = (t & 31) * 4;
    const float* bptr = w1 + ((size_t)e * D + bk) * H + n0 + bn;

    float4 areg = make_float4(0.f, 0.f, 0.f, 0.f);
    if (aptr) areg = *(const float4*)aptr;
    float4 breg = *(const float4*)bptr;

    As[0][ahalf + 0][arow] = areg.x;
    As[0][ahalf + 1][arow] = areg.y;
    As[0][ahalf + 2][arow] = areg.z;
    As[0][ahalf + 3][arow] = areg.w;
    *(float4*)&Bs[0][bk][bn] = breg;
    __syncthreads();

    const int ty = t >> 4, tx = t & 15;
    float acc[8][8];
    #pragma unroll
    for (int i = 0; i < 8; i++)
        #pragma unroll
        for (int j = 0; j < 8; j++) acc[i][j] = 0.f;

    int buf = 0;
    for (int kk = 8; kk <= D; kk += 8) {
        const bool more = (kk < D);
        if (more) {
            areg = make_float4(0.f, 0.f, 0.f, 0.f);
            if (aptr) areg = *(const float4*)(aptr + kk);
            breg = *(const float4*)(bptr + (size_t)kk * H);
        }
        #pragma unroll
        for (int k = 0; k < 8; k++) {
            float a[8], b[8];
            *(float4*)&a[0] = *(const float4*)&As[buf][k][ty * 8];
            *(float4*)&a[4] = *(const float4*)&As[buf][k][ty * 8 + 4];
            *(float4*)&b[0] = *(const float4*)&Bs[buf][k][tx * 8];
            *(float4*)&b[4] = *(const float4*)&Bs[buf][k][tx * 8 + 4];
            #pragma unroll
            for (int i = 0; i < 8; i++)
                #pragma unroll
                for (int j = 0; j < 8; j++)
                    acc[i][j] = fmaf(a[i], b[j], acc[i][j]);
        }
        if (more) {
            const int nb = buf ^ 1;
            As[nb][ahalf + 0][arow] = areg.x;
            As[nb][ahalf + 1][arow] = areg.y;
            As[nb][ahalf + 2][arow] = areg.z;
            As[nb][ahalf + 3][arow] = areg.w;
            *(float4*)&Bs[nb][bk][bn] = breg;
        }
        __syncthreads();
        buf ^= 1;
    }

    // Epilogue: relu(acc + b1) . w2sum, reduced across the 16 tx columns.
    float bv[8], wv[8];
    {
        const float* bp = b1 + (size_t)e * H + n0 + tx * 8;
        const float* wp = g_w2sum + (size_t)e * H + n0 + tx * 8;
        *(float4*)&bv[0] = *(const float4*)bp;
        *(float4*)&bv[4] = *(const float4*)(bp + 4);
        *(float4*)&wv[0] = *(const float4*)wp;
        *(float4*)&wv[4] = *(const float4*)(wp + 4);
    }
    float* red = &As[0][0][0];  // 2112 floats available, need 2048
    #pragma unroll
    for (int i = 0; i < 8; i++) {
        float sr = 0.f;
        #pragma unroll
        for (int j = 0; j < 8; j++)
            sr += fmaxf(acc[i][j] + bv[j], 0.f) * wv[j];
        red[tx * 128 + ty * 8 + i] = sr;
    }
    __syncthreads();
    if (t < 128) {
        float ssum = 0.f;
        #pragma unroll
        for (int q = 0; q < 16; q++) ssum += red[q * 128 + t];
        g_part[(size_t)(e * CAP + m0 + t) * NTILES + blockIdx.x] = ssum;
    }
}

// ---------------- K4a: per-token logit = sum over D of y ----------------
__global__ void k_logit() {
    int s = blockIdx.x * blockDim.x + threadIdx.x;
    if (s >= S) return;
    float l = 0.f;
    #pragma unroll
    for (int k = 0; k < KK; k++) {
        int slot = g_tokslot[k * S + s];
        if (slot >= 0) {
            float c = 0.f;
            const float* p = g_part + (size_t)slot * NTILES;
            #pragma unroll
            for (int j = 0; j < NTILES; j++) c += p[j];
            l += g_wgt[k * S + s] * (c + g_b2sum[g_eid[k * S + s]]);
        }
    }
    g_logit[s] = l;
}

// ---------------- K4b: log_softmax over T per batch row -----------------
__global__ void k_lsm(float* __restrict__ out) {
    const int b = blockIdx.x;
    const int t = threadIdx.x;  // 256 threads
    __shared__ float sh[256];
    const float* lr = g_logit + (size_t)b * T;
    float v[8];
    float mx = -INFINITY;
    #pragma unroll
    for (int i = 0; i < 8; i++) {
        v[i] = lr[t + i * 256];
        mx = fmaxf(mx, v[i]);
    }
    sh[t] = mx;
    __syncthreads();
    for (int o = 128; o; o >>= 1) {
        if (t < o) sh[t] = fmaxf(sh[t], sh[t + o]);
        __syncthreads();
    }
    mx = sh[0];
    __syncthreads();
    float se = 0.f;
    #pragma unroll
    for (int i = 0; i < 8; i++) se += expf(v[i] - mx);
    sh[t] = se;
    __syncthreads();
    for (int o = 128; o; o >>= 1) {
        if (t < o) sh[t] += sh[t + o];
        __syncthreads();
    }
    float lse = logf(sh[0]) + mx;
    #pragma unroll
    for (int i = 0; i < 8; i++)
        out[(size_t)b * T + t + i * 256] = v[i] - lse;
}

// ---------------- launch ------------------------------------------------
extern "C" void kernel_launch(void* const* d_in, const int* in_sizes, int n_in,
                              void* d_out, int out_size) {
    const float* x  = (const float*)d_in[0];   // [B,T,D]
    const float* wg = (const float*)d_in[1];   // [D,E]
    const float* w1 = (const float*)d_in[2];   // [E,D,H]
    const float* b1 = (const float*)d_in[3];   // [E,H]
    const float* w2 = (const float*)d_in[4];   // [E,H,D]
    const float* b2 = (const float*)d_in[5];   // [E,D]
    float* out = (float*)d_out;                // [B,T]
    (void)in_sizes; (void)n_in; (void)out_size;

    float* w2sum_p; cudaGetSymbolAddress((void**)&w2sum_p, g_w2sum);
    float* b2sum_p; cudaGetSymbolAddress((void**)&b2sum_p, g_b2sum);

    // K0: w2 row sums (E*H rows of length D) and b2 sums (E rows)
    k_rowsum<<<(E * H) / 8, 256>>>(w2, w2sum_p, E * H);
    k_rowsum<<<1, 256>>>(b2, b2sum_p, E);

    // K1: gating, one warp per token
    k_gate<<<S / 8, 256>>>(x, wg);

    // K2: deterministic capacity assignment, single block
    k_assign<<<1, 256>>>();

    // K3: grouped expert GEMM + fused reduction
    dim3 g3(H / 128, CAP / 128, E);
    k_ffn<<<g3, 256>>>(x, w1, b1);

    // K4: combine + log_softmax
    k_logit<<<S / 256, 256>>>();
    k_lsm<<<B, 256>>>(out);
}

// round 3
// speedup vs baseline: 1.0559x; 1.0004x over previous
#include <cuda_runtime.h>
#include <cuda_bf16.h>
#include <cstdint>
#include <math.h>

// Problem dims (fixed by the dataset)
constexpr int S  = 8192;   // B*T tokens
constexpr int D  = 2048;   // model dim
constexpr int H  = 2048;   // expert hidden
constexpr int E  = 8;      // experts
constexpr int KK = 2;      // top-k
constexpr int CAP = 2048;  // per-expert capacity
constexpr int B  = 4;
constexpr int T  = 2048;
constexpr int NTILES = H / 128;  // 16 N-tiles per expert row

// ---------------- device scratch (no allocations allowed) ----------------
__device__ int   g_eid[KK * S];
__device__ float g_wgt[KK * S];
__device__ int   g_src[E * CAP];       // slot -> source token (-1 = empty)
__device__ int   g_tokslot[KK * S];    // (k,s) -> slot index or -1
__device__ float g_w2sum[E * H];
__device__ float g_b2sum[E];
__device__ float g_part[(size_t)E * CAP * NTILES];
__device__ float g_logit[S];

// ---------------- K0: row sums of w2 (and b2) --------------------------
__global__ void k_rowsum(const float* __restrict__ src, float* __restrict__ dst,
                         int nrows) {
    int gw   = (blockIdx.x * blockDim.x + threadIdx.x) >> 5;
    int lane = threadIdx.x & 31;
    if (gw >= nrows) return;
    const float* row = src + (size_t)gw * D;
    float s = 0.f;
    #pragma unroll
    for (int d = lane * 4; d < D; d += 32 * 4) {
        float4 v = *(const float4*)(row + d);
        s += v.x + v.y + v.z + v.w;
    }
    #pragma unroll
    for (int o = 16; o; o >>= 1) s += __shfl_xor_sync(0xffffffffu, s, o);
    if (lane == 0) dst[gw] = s;
}

// ---------------- K1: gating (top-2 of softmax(x@wg), normalized) ------
__global__ void k_gate(const float* __restrict__ x, const float* __restrict__ wg) {
    int warp = (blockIdx.x * blockDim.x + threadIdx.x) >> 5;
    int lane = threadIdx.x & 31;
    if (warp >= S) return;
    const float* xr = x + (size_t)warp * D;
    float acc[8] = {0, 0, 0, 0, 0, 0, 0, 0};
    for (int d = lane; d < D; d += 32) {
        float xv = xr[d];
        const float* wr = wg + (size_t)d * 8;
        float4 w0 = *(const float4*)wr;
        float4 w1 = *(const float4*)(wr + 4);
        acc[0] = fmaf(xv, w0.x, acc[0]);
        acc[1] = fmaf(xv, w0.y, acc[1]);
        acc[2] = fmaf(xv, w0.z, acc[2]);
        acc[3] = fmaf(xv, w0.w, acc[3]);
        acc[4] = fmaf(xv, w1.x, acc[4]);
        acc[5] = fmaf(xv, w1.y, acc[5]);
        acc[6] = fmaf(xv, w1.z, acc[6]);
        acc[7] = fmaf(xv, w1.w, acc[7]);
    }
    #pragma unroll
    for (int ee = 0; ee < 8; ee++)
        #pragma unroll
        for (int o = 16; o; o >>= 1)
            acc[ee] += __shfl_xor_sync(0xffffffffu, acc[ee], o);
    if (lane == 0) {
        // top-1 (strict > keeps lowest index on ties, matching lax.top_k)
        int i0 = 0; float v0 = acc[0];
        #pragma unroll
        for (int ee = 1; ee < 8; ee++)
            if (acc[ee] > v0) { v0 = acc[ee]; i0 = ee; }
        int i1 = -1; float v1 = -INFINITY;
        #pragma unroll
        for (int ee = 0; ee < 8; ee++)
            if (ee != i0 && acc[ee] > v1) { v1 = acc[ee]; i1 = ee; }
        // normalized top-2 softmax weights: w0 = e^{v0}/(e^{v0}+e^{v1})
        float w0 = 1.f / (1.f + __expf(0.f) * expf(v1 - v0));
        g_eid[warp]     = i0;
        g_eid[S + warp] = i1;
        g_wgt[warp]     = w0;
        g_wgt[S + warp] = 1.f - w0;
    }
}

// ---------------- K2: capacity-aware slot assignment (one block) -------
// Exact k-major, s-minor rank per expert (matches cumsum semantics).
__global__ void k_assign() {
    __shared__ int hist[256][8];
    const int t = threadIdx.x;
    // init slot map
    for (int i = t; i < E * CAP; i += 256) g_src[i] = -1;
    // local histogram over this thread's 64 consecutive (k-major) entries
    int h[8] = {0, 0, 0, 0, 0, 0, 0, 0};
    const int base = t * 64;
    for (int j = 0; j < 64; j++) h[g_eid[base + j]]++;
    #pragma unroll
    for (int ee = 0; ee < 8; ee++) hist[t][ee] = h[ee];
    __syncthreads();
    // exclusive scan over chunks, per expert (serial, tiny)
    if (t < 8) {
        int run = 0;
        for (int c = 0; c < 256; c++) {
            int v = hist[c][t];
            hist[c][t] = run;
            run += v;
        }
    }
    __syncthreads();
    int cnt[8];
    #pragma unroll
    for (int ee = 0; ee < 8; ee++) cnt[ee] = hist[t][ee];
    for (int j = 0; j < 64; j++) {
        int n = base + j;
        int e = g_eid[n];
        int loc = cnt[e]++;
        if (loc < CAP) {
            g_src[e * CAP + loc] = n & (S - 1);  // token s
            g_tokslot[n] = e * CAP + loc;
        } else {
            g_tokslot[n] = -1;
        }
    }
}

// ---------------- K3: fused expert GEMM + epilogue reduction -----------
// grid = (H/128, CAP/128, E). Block computes 128x128 tile of
// h = relu(gather(x) @ w1[e] + b1[e]) and reduces h . w2sum[e] per row,
// writing one partial per (slot, n-tile) into g_part. No atomics.
__global__ void __launch_bounds__(256, 2)
k_ffn(const float* __restrict__ x, const float* __restrict__ w1,
      const float* __restrict__ b1) {
    const int e  = blockIdx.z;
    const int m0 = blockIdx.y * 128;
    const int n0 = blockIdx.x * 128;
    const int t  = threadIdx.x;

    __shared__ float As[2][8][132];  // padded (+4) to dodge STS conflicts
    __shared__ float Bs[2][8][128];

    // A loader: 128 rows x 8 k per tile; 2 threads per row
    const int arow  = t >> 1;
    const int ahalf = (t & 1) * 4;
    const int stok  = g_src[e * CAP + m0 + arow];
    const float* aptr = (stok >= 0) ? (x + (size_t)stok * D + ahalf) : nullptr;

    // B loader: 8 k x 128 n per tile
    const int bk = t >> 5;
    const int bn = (t & 31) * 4;
    const float* bptr = w1 + ((size_t)e * D + bk) * H + n0 + bn;

    float4 areg = make_float4(0.f, 0.f, 0.f, 0.f);
    if (aptr) areg = *(const float4*)aptr;
    float4 breg = *(const float4*)bptr;

    As[0][ahalf + 0][arow] = areg.x;
    As[0][ahalf + 1][arow] = areg.y;
    As[0][ahalf + 2][arow] = areg.z;
    As[0][ahalf + 3][arow] = areg.w;
    *(float4*)&Bs[0][bk][bn] = breg;
    __syncthreads();

    const int ty = t >> 4, tx = t & 15;
    float acc[8][8];
    #pragma unroll
    for (int i = 0; i < 8; i++)
        #pragma unroll
        for (int j = 0; j < 8; j++) acc[i][j] = 0.f;

    int buf = 0;
    for (int kk = 8; kk <= D; kk += 8) {
        const bool more = (kk < D);
        if (more) {
            areg = make_float4(0.f, 0.f, 0.f, 0.f);
            if (aptr) areg = *(const float4*)(aptr + kk);
            breg = *(const float4*)(bptr + (size_t)kk * H);
        }
        #pragma unroll
        for (int k = 0; k < 8; k++) {
            float a[8], b[8];
            *(float4*)&a[0] = *(const float4*)&As[buf][k][ty * 8];
            *(float4*)&a[4] = *(const float4*)&As[buf][k][ty * 8 + 4];
            *(float4*)&b[0] = *(const float4*)&Bs[buf][k][tx * 8];
            *(float4*)&b[4] = *(const float4*)&Bs[buf][k][tx * 8 + 4];
            #pragma unroll
            for (int i = 0; i < 8; i++)
                #pragma unroll
                for (int j = 0; j < 8; j++)
                    acc[i][j] = fmaf(a[i], b[j], acc[i][j]);
        }
        if (more) {
            const int nb = buf ^ 1;
            As[nb][ahalf + 0][arow] = areg.x;
            As[nb][ahalf + 1][arow] = areg.y;
            As[nb][ahalf + 2][arow] = areg.z;
            As[nb][ahalf + 3][arow] = areg.w;
            *(float4*)&Bs[nb][bk][bn] = breg;
        }
        __syncthreads();
        buf ^= 1;
    }

    // Epilogue: relu(acc + b1) . w2sum, reduced across the 16 tx columns.
    float bv[8], wv[8];
    {
        const float* bp = b1 + (size_t)e * H + n0 + tx * 8;
        const float* wp = g_w2sum + (size_t)e * H + n0 + tx * 8;
        *(float4*)&bv[0] = *(const float4*)bp;
        *(float4*)&bv[4] = *(const float4*)(bp + 4);
        *(float4*)&wv[0] = *(const float4*)wp;
        *(float4*)&wv[4] = *(const float4*)(wp + 4);
    }
    float* red = &As[0][0][0];  // 2112 floats available, need 2048
    #pragma unroll
    for (int i = 0; i < 8; i++) {
        float sr = 0.f;
        #pragma unroll
        for (int j = 0; j < 8; j++)
            sr += fmaxf(acc[i][j] + bv[j], 0.f) * wv[j];
        red[tx * 128 + ty * 8 + i] = sr;
    }
    __syncthreads();
    if (t < 128) {
        float ssum = 0.f;
        #pragma unroll
        for (int q = 0; q < 16; q++) ssum += red[q * 128 + t];
        g_part[(size_t)(e * CAP + m0 + t) * NTILES + blockIdx.x] = ssum;
    }
}

// ---------------- K4a: per-token logit = sum over D of y ----------------
__global__ void k_logit() {
    int s = blockIdx.x * blockDim.x + threadIdx.x;
    if (s >= S) return;
    float l = 0.f;
    #pragma unroll
    for (int k = 0; k < KK; k++) {
        int slot = g_tokslot[k * S + s];
        if (slot >= 0) {
            float c = 0.f;
            const float* p = g_part + (size_t)slot * NTILES;
            #pragma unroll
            for (int j = 0; j < NTILES; j++) c += p[j];
            l += g_wgt[k * S + s] * (c + g_b2sum[g_eid[k * S + s]]);
        }
    }
    g_logit[s] = l;
}

// ---------------- K4b: log_softmax over T per batch row -----------------
__global__ void k_lsm(float* __restrict__ out) {
    const int b = blockIdx.x;
    const int t = threadIdx.x;  // 256 threads
    __shared__ float sh[256];
    const float* lr = g_logit + (size_t)b * T;
    float v[8];
    float mx = -INFINITY;
    #pragma unroll
    for (int i = 0; i < 8; i++) {
        v[i] = lr[t + i * 256];
        mx = fmaxf(mx, v[i]);
    }
    sh[t] = mx;
    __syncthreads();
    for (int o = 128; o; o >>= 1) {
        if (t < o) sh[t] = fmaxf(sh[t], sh[t + o]);
        __syncthreads();
    }
    mx = sh[0];
    __syncthreads();
    float se = 0.f;
    #pragma unroll
    for (int i = 0; i < 8; i++) se += expf(v[i] - mx);
    sh[t] = se;
    __syncthreads();
    for (int o = 128; o; o >>= 1) {
        if (t < o) sh[t] += sh[t + o];
        __syncthreads();
    }
    float lse = logf(sh[0]) + mx;
    #pragma unroll
    for (int i = 0; i < 8; i++)
        out[(size_t)b * T + t + i * 256] = v[i] - lse;
}

// ---------------- launch ------------------------------------------------
extern "C" void kernel_launch(void* const* d_in, const int* in_sizes, int n_in,
                              void* d_out, int out_size) {
    const float* x  = (const float*)d_in[0];   // [B,T,D]
    const float* wg = (const float*)d_in[1];   // [D,E]
    const float* w1 = (const float*)d_in[2];   // [E,D,H]
    const float* b1 = (const float*)d_in[3];   // [E,H]
    const float* w2 = (const float*)d_in[4];   // [E,H,D]
    const float* b2 = (const float*)d_in[5];   // [E,D]
    float* out = (float*)d_out;                // [B,T]
    (void)in_sizes; (void)n_in; (void)out_size;

    float* w2sum_p; cudaGetSymbolAddress((void**)&w2sum_p, g_w2sum);
    float* b2sum_p; cudaGetSymbolAddress((void**)&b2sum_p, g_b2sum);

    // K0: w2 row sums (E*H rows of length D) and b2 sums (E rows)
    k_rowsum<<<(E * H) / 8, 256>>>(w2, w2sum_p, E * H);
    k_rowsum<<<1, 256>>>(b2, b2sum_p, E);

    // K1: gating, one warp per token
    k_gate<<<S / 8, 256>>>(x, wg);

    // K2: deterministic capacity assignment, single block
    k_assign<<<1, 256>>>();

    // K3: grouped expert GEMM + fused reduction
    dim3 g3(H / 128, CAP / 128, E);
    k_ffn<<<g3, 256>>>(x, w1, b1);

    // K4: combine + log_softmax
    k_logit<<<S / 256, 256>>>();
    k_lsm<<<B, 256>>>(out);
}